// round 16
// baseline (speedup 1.0000x reference)
#include <cuda_runtime.h>
#include <cuda_fp16.h>
#include <cuda_bf16.h>
#include <math.h>

// ---------------- problem constants ----------------
#define NN      15000
#define NE      60000
#define DIN     74
#define DEI     12
#define DD      64
#define EH      128
#define NSTEPS  6
#define BN_EPS  1e-5f

// ---------------- scratch (device globals; allocation-free) ----------------
__device__ float  g_H[NN * DD];
__device__ __half g_Ah[NE * EH];                 // edge hidden a, DST-SORTED order
__device__ __half g_W2h[EH * DD * DD];           // W_e2 fp16 (1 MB, L2-resident)
__device__ __half g_EWh[(size_t)NE * DD * DD];   // per-edge matrices, sorted (492 MB)
__device__ float  g_RST[NN * DD];
__device__ int    g_cnt[NN];
__device__ int    g_off[NN + 1];
__device__ int    g_cur[NN];
__device__ int    g_pos[NE];                     // edge -> sorted slot
__device__ int    g_srcs[NE];                    // src per sorted slot
__device__ float  g_colsum[DD];
__device__ float  g_colsq[DD];
__device__ float  g_bnscale[DD];
__device__ float  g_bnshift[DD];
__device__ unsigned g_bnctr;

// ---------------- f32x2 packed-FMA helpers (Blackwell FFMA2) ----------------
__device__ __forceinline__ unsigned long long fma2(unsigned long long a,
                                                   unsigned long long b,
                                                   unsigned long long c) {
    unsigned long long d;
    asm("fma.rn.f32x2 %0, %1, %2, %3;" : "=l"(d) : "l"(a), "l"(b), "l"(c));
    return d;
}
__device__ __forceinline__ float2 unpack2(unsigned long long v) {
    float2 f;
    asm("mov.b64 {%0, %1}, %2;" : "=f"(f.x), "=f"(f.y) : "l"(v));
    return f;
}

// ---------------- tensor-core helpers ----------------
__device__ __forceinline__ unsigned smem_u32(const void* p) {
    return (unsigned)__cvta_generic_to_shared(p);
}
__device__ __forceinline__ void ldmA(unsigned& a0, unsigned& a1, unsigned& a2,
                                     unsigned& a3, unsigned addr) {
    asm volatile("ldmatrix.sync.aligned.m8n8.x4.shared.b16 {%0,%1,%2,%3}, [%4];"
                 : "=r"(a0), "=r"(a1), "=r"(a2), "=r"(a3) : "r"(addr));
}
__device__ __forceinline__ void ldmBT(unsigned& b0, unsigned& b1, unsigned& b2,
                                      unsigned& b3, unsigned addr) {
    asm volatile("ldmatrix.sync.aligned.m8n8.x4.trans.shared.b16 {%0,%1,%2,%3}, [%4];"
                 : "=r"(b0), "=r"(b1), "=r"(b2), "=r"(b3) : "r"(addr));
}
__device__ __forceinline__ void mma16816(float& c0, float& c1, float& c2, float& c3,
                                         unsigned a0, unsigned a1, unsigned a2,
                                         unsigned a3, unsigned b0, unsigned b1) {
    asm volatile(
        "mma.sync.aligned.m16n8k16.row.col.f32.f16.f16.f32 "
        "{%0,%1,%2,%3}, {%4,%5,%6,%7}, {%8,%9}, {%0,%1,%2,%3};"
        : "+f"(c0), "+f"(c1), "+f"(c2), "+f"(c3)
        : "r"(a0), "r"(a1), "r"(a2), "r"(a3), "r"(b0), "r"(b1));
}

// ---------------- prep kernels ----------------
__global__ void k_zero() {
    int i = blockIdx.x * blockDim.x + threadIdx.x;
    if (i < NN) g_cnt[i] = 0;
    if (i < DD) { g_colsum[i] = 0.f; g_colsq[i] = 0.f; }
    if (i == 0) g_bnctr = 0u;
}

__global__ void k_cnt(const int* __restrict__ dst) {
    int e = blockIdx.x * blockDim.x + threadIdx.x;
    if (e < NE) atomicAdd(&g_cnt[dst[e]], 1);
}

// exclusive scan of g_cnt -> g_off / g_cur (single block, 1024 threads, 15/thread)
__global__ void __launch_bounds__(1024) k_scan() {
    __shared__ int ps[1024];
    int t = threadIdx.x;
    int base = t * 15;
    int loc[15];
    int s = 0;
#pragma unroll
    for (int j = 0; j < 15; ++j) {
        int n = base + j;
        int c = (n < NN) ? g_cnt[n] : 0;
        loc[j] = s;
        s += c;
    }
    ps[t] = s;
    __syncthreads();
    for (int off = 1; off < 1024; off <<= 1) {
        int v = (t >= off) ? ps[t - off] : 0;
        __syncthreads();
        ps[t] += v;
        __syncthreads();
    }
    int excl = (t == 0) ? 0 : ps[t - 1];
#pragma unroll
    for (int j = 0; j < 15; ++j) {
        int n = base + j;
        if (n < NN) {
            int o = excl + loc[j];
            g_off[n] = o;
            g_cur[n] = o;
        }
    }
    if (t == 1023) g_off[NN] = ps[1023];
}

__global__ void k_scatter(const int* __restrict__ src, const int* __restrict__ dst) {
    int e = blockIdx.x * blockDim.x + threadIdx.x;
    if (e < NE) {
        int d = dst[e];
        int p = atomicAdd(&g_cur[d], 1);
        g_pos[e] = p;
        g_srcs[p] = src[e];
    }
}

// ---------------- fused static precompute: edge1(sorted) + proj + w2cvt -----
#define PREP_PROJ_BLKS  ((NN + 1) / 2)
#define PREP_W2_BLKS    (EH * DD * DD / 128)
#define PREP_BLOCKS     (NE + PREP_PROJ_BLKS + PREP_W2_BLKS)

__global__ void __launch_bounds__(128) k_prep(
    const float* __restrict__ ef, const float* __restrict__ W1,
    const float* __restrict__ b1,
    const float* __restrict__ nf, const float* __restrict__ Wp,
    const float* __restrict__ bp,
    const float* __restrict__ W2) {
    int b = blockIdx.x;
    int tid = threadIdx.x;
    if (b < NE) {
        int p = g_pos[b];
        int k = tid;
        const float* row = ef + (size_t)b * DEI;
        float acc = b1[k];
#pragma unroll
        for (int i = 0; i < DEI; ++i)
            acc = fmaf(__ldg(&row[i]), __ldg(&W1[i * EH + k]), acc);
        g_Ah[(size_t)p * EH + k] = __float2half_rn(fmaxf(acc, 0.f));
    } else if (b < NE + PREP_PROJ_BLKS) {
        int r = (b - NE) * 2 + (tid >> 6);
        int o = tid & 63;
        if (r < NN) {
            const float* row = nf + (size_t)r * DIN;
            float acc = bp[o];
#pragma unroll 2
            for (int i = 0; i < DIN; ++i)
                acc = fmaf(__ldg(&row[i]), __ldg(&Wp[i * DD + o]), acc);
            g_H[(size_t)r * DD + o] = fmaxf(acc, 0.f);
        }
    } else {
        int idx = (b - NE - PREP_PROJ_BLKS) * 128 + tid;
        g_W2h[idx] = __float2half_rn(W2[idx]);
    }
}

// ---------------- edge MLP stage 2 on tensor cores (unchanged) --------------
#define E2_AS_BYTES    (128 * 136 * 2)
#define E2_B_BYTES     (128 * 72 * 2)
#define E2_BT_BYTES    (E2_B_BYTES + 256)
#define E2_STAGE_OFF   (E2_AS_BYTES + 2 * E2_BT_BYTES)
#define E2_STAGE_BYTES (128 * 72 * 2)
#define E2_SMEM_TOTAL  (E2_STAGE_OFF + E2_STAGE_BYTES)   // 90624 -> 2 blocks/SM

__device__ __forceinline__ void e2_stage(char* sm, int p, int ntile, int tid,
                                         const float* __restrict__ b2) {
    __half* B = reinterpret_cast<__half*>(sm + E2_AS_BYTES + p * E2_BT_BYTES);
    float* bias = reinterpret_cast<float*>(sm + E2_AS_BYTES + p * E2_BT_BYTES + E2_B_BYTES);
    int n0 = ntile * 64;
#pragma unroll
    for (int r = 0; r < 4; ++r) {
        int i = tid + r * 256;
        int row = i >> 3, seg = i & 7;
        const __half* src = &g_W2h[(size_t)row * 4096 + n0 + seg * 8];
        unsigned da = smem_u32(B + row * 72 + seg * 8);
        asm volatile("cp.async.cg.shared.global [%0], [%1], 16;" :: "r"(da), "l"(src));
    }
    if (tid < 16) {
        const float* src = b2 + n0 + tid * 4;
        unsigned da = smem_u32(bias + tid * 4);
        asm volatile("cp.async.cg.shared.global [%0], [%1], 16;" :: "r"(da), "l"(src));
    }
    asm volatile("cp.async.commit_group;");
}

__global__ void __launch_bounds__(256, 2) k_edge2t(const float* __restrict__ b2) {
    extern __shared__ char sm[];
    __half (*As)[136] = reinterpret_cast<__half(*)[136]>(sm);
    __half* stg = reinterpret_cast<__half*>(sm + E2_STAGE_OFF);

    int tid  = threadIdx.x;
    int warp = tid >> 5;
    int lane = tid & 31;
    int warpM = warp >> 1;
    int warpN = warp & 1;
    int e0 = blockIdx.x * 128;

#pragma unroll
    for (int r = 0; r < 8; ++r) {
        int i = tid + r * 256;
        int row = i >> 4, seg = i & 15;
        int e = e0 + row;
        uint4 v = (e < NE)
            ? *reinterpret_cast<const uint4*>(&g_Ah[(size_t)e * EH + seg * 8])
            : make_uint4(0u, 0u, 0u, 0u);
        *reinterpret_cast<uint4*>(&As[row][seg * 8]) = v;
    }

    e2_stage(sm, 0, 0, tid, b2);
    __syncthreads();

    unsigned afr[2][8][4];
#pragma unroll
    for (int mt = 0; mt < 2; ++mt) {
        unsigned aBase = smem_u32(&As[warpM * 32 + mt * 16 + (lane & 15)][(lane >> 4) * 8]);
#pragma unroll
        for (int ks = 0; ks < 8; ++ks)
            ldmA(afr[mt][ks][0], afr[mt][ks][1], afr[mt][ks][2], afr[mt][ks][3],
                 aBase + ks * 32);
    }

    unsigned bOff = (lane & 15) * 144 + (lane >> 4) * 16 + warpN * 64;
    int frl = warpM * 32 + (lane >> 2);
    int cb = (lane & 3) * 2;

    for (int ntile = 0; ntile < 64; ++ntile) {
        int buf = ntile & 1;
        asm volatile("cp.async.wait_group 0;");
        __syncthreads();

        if (ntile + 1 < 64)
            e2_stage(sm, buf ^ 1, ntile + 1, tid, b2);

        float acc[2][4][4];
#pragma unroll
        for (int mt = 0; mt < 2; ++mt)
#pragma unroll
            for (int t = 0; t < 4; ++t)
#pragma unroll
                for (int p = 0; p < 4; ++p) acc[mt][t][p] = 0.f;

        unsigned bBase = smem_u32(sm + E2_AS_BYTES + buf * E2_BT_BYTES) + bOff;
#pragma unroll
        for (int ks = 0; ks < 8; ++ks) {
#pragma unroll
            for (int nt = 0; nt < 2; ++nt) {
                unsigned b0, b1, b2v, b3;
                ldmBT(b0, b1, b2v, b3, bBase + ks * 16 * 144 + nt * 32);
#pragma unroll
                for (int mt = 0; mt < 2; ++mt) {
                    mma16816(acc[mt][nt * 2][0], acc[mt][nt * 2][1],
                             acc[mt][nt * 2][2], acc[mt][nt * 2][3],
                             afr[mt][ks][0], afr[mt][ks][1], afr[mt][ks][2],
                             afr[mt][ks][3], b0, b1);
                    mma16816(acc[mt][nt * 2 + 1][0], acc[mt][nt * 2 + 1][1],
                             acc[mt][nt * 2 + 1][2], acc[mt][nt * 2 + 1][3],
                             afr[mt][ks][0], afr[mt][ks][1], afr[mt][ks][2],
                             afr[mt][ks][3], b2v, b3);
                }
            }
        }

        const float* bias = reinterpret_cast<const float*>(
            sm + E2_AS_BYTES + buf * E2_BT_BYTES + E2_B_BYTES);
#pragma unroll
        for (int mt = 0; mt < 2; ++mt) {
            int lr = frl + mt * 16;
#pragma unroll
            for (int cg = 0; cg < 4; ++cg) {
                int lc = warpN * 32 + cg * 8 + cb;
                float2 bv = *reinterpret_cast<const float2*>(&bias[lc]);
                __half2 h0 = __floats2half2_rn(acc[mt][cg][0] + bv.x,
                                               acc[mt][cg][1] + bv.y);
                __half2 h1 = __floats2half2_rn(acc[mt][cg][2] + bv.x,
                                               acc[mt][cg][3] + bv.y);
                *reinterpret_cast<__half2*>(&stg[lr * 72 + lc]) = h0;
                *reinterpret_cast<__half2*>(&stg[(lr + 8) * 72 + lc]) = h1;
            }
        }
        __syncthreads();

        int n0 = ntile * 64;
#pragma unroll
        for (int r = 0; r < 4; ++r) {
            int c = tid + r * 256;
            int row = c >> 3, seg = c & 7;
            if (e0 + row < NE) {
                uint4 v = *reinterpret_cast<const uint4*>(&stg[row * 72 + seg * 8]);
                __stcs(reinterpret_cast<uint4*>(
                           &g_EWh[(size_t)(e0 + row) * 4096 + n0 + seg * 8]), v);
            }
        }
    }
}

// ---------------- fused per-step message + mean + bias + BN stats ------------
// Warp owns 4 dst nodes (CSR); accumulates all their edges, no atomics on RST.
// Last block finalizes BN scale/shift.
__global__ void __launch_bounds__(512) k_msgf(const float* __restrict__ cbias,
                                              const float* __restrict__ gamma,
                                              const float* __restrict__ beta) {
    __shared__ float cs[64], cq[64];
    __shared__ int s_last;
    int tid = threadIdx.x;
    int w = tid >> 5, lane = tid & 31;
    if (tid < 64) { cs[tid] = 0.f; cq[tid] = 0.f; }
    __syncthreads();

    int r = lane >> 3;
    int c = lane & 7;
    int q0 = r * 2;
    int col = c * 8 + q0;
    float cb0 = __ldg(&cbias[col]);
    float cb1 = __ldg(&cbias[col + 1]);

    int vbase = blockIdx.x * 64 + w * 4;
#pragma unroll 1
    for (int nv = 0; nv < 4; ++nv) {
        int v = vbase + nv;
        if (v >= NN) break;                      // uniform within warp
        int d0 = g_off[v];
        int d1 = g_off[v + 1];
        float acc[8];
#pragma unroll
        for (int q = 0; q < 8; ++q) acc[q] = 0.f;

        for (int e = d0; e < d1; ++e) {
            int s = g_srcs[e];
            float hv0 = g_H[(size_t)s * DD + lane];
            float hv1 = g_H[(size_t)s * DD + 32 + lane];
            const uint4* M = reinterpret_cast<const uint4*>(g_EWh + (size_t)e * 4096) + c;
#pragma unroll
            for (int t = 0; t < 16; ++t) {
                int i = t * 4 + r;
                uint4 wv = __ldcs(&M[i * 8]);
                float hv = __shfl_sync(0xffffffffu, (t < 8) ? hv0 : hv1, i & 31);
                const __half2* hp = reinterpret_cast<const __half2*>(&wv);
#pragma unroll
                for (int q = 0; q < 4; ++q) {
                    float2 f = __half22float2(hp[q]);
                    acc[2 * q]     = fmaf(hv, f.x, acc[2 * q]);
                    acc[2 * q + 1] = fmaf(hv, f.y, acc[2 * q + 1]);
                }
            }
        }
#pragma unroll
        for (int q = 0; q < 8; ++q) {
            acc[q] += __shfl_xor_sync(0xffffffffu, acc[q], 8);
            acc[q] += __shfl_xor_sync(0xffffffffu, acc[q], 16);
        }
        int dd = d1 - d0;
        float inv = (dd > 0) ? (1.f / (float)dd) : 0.f;
        float x0 = fmaf(acc[q0], inv, cb0);
        float x1 = fmaf(acc[q0 + 1], inv, cb1);
        float* out = g_RST + (size_t)v * DD + col;
        out[0] = x0;
        out[1] = x1;
        atomicAdd(&cs[col], x0);
        atomicAdd(&cs[col + 1], x1);
        atomicAdd(&cq[col], x0 * x0);
        atomicAdd(&cq[col + 1], x1 * x1);
    }
    __syncthreads();
    if (tid < 64) {
        atomicAdd(&g_colsum[tid], cs[tid]);
        atomicAdd(&g_colsq[tid], cq[tid]);
    }
    __syncthreads();
    if (tid == 0) {
        __threadfence();
        unsigned t = atomicAdd(&g_bnctr, 1u);
        s_last = (t == gridDim.x - 1);
    }
    __syncthreads();
    if (s_last) {
        __threadfence();
        if (tid < 64) {
            const float invn = 1.f / (float)NN;
            float mu = g_colsum[tid] * invn;
            float var = g_colsq[tid] * invn - mu * mu;
            float sc = gamma[tid] * rsqrtf(var + BN_EPS);
            g_bnscale[tid] = sc;
            g_bnshift[tid] = beta[tid] - mu * sc;
            g_colsum[tid] = 0.f;
            g_colsq[tid] = 0.f;
        }
        if (tid == 0) g_bnctr = 0u;
    }
}

// GRU; 2 nodes per barrier iteration; 64 nodes/block
__global__ void __launch_bounds__(192) k_gru(const float* __restrict__ W_ih,
                                             const float* __restrict__ W_hh,
                                             const float* __restrict__ b_ih,
                                             const float* __restrict__ b_hh,
                                             float* __restrict__ out, int last) {
    __shared__ float m_s[2][64], h_s[2][64], gi_s[2][192], gh_s[2][192];
    int j = threadIdx.x;

    unsigned long long wih[32], whh[32];
    const unsigned long long* pih = reinterpret_cast<const unsigned long long*>(W_ih) + j * 32;
    const unsigned long long* phh = reinterpret_cast<const unsigned long long*>(W_hh) + j * 32;
#pragma unroll
    for (int q = 0; q < 32; ++q) { wih[q] = pih[q]; whh[q] = phh[q]; }
    float bi = b_ih[j], bh = b_hh[j];
    float sc = 0.f, sh = 0.f;
    if (j < 64) { sc = g_bnscale[j]; sh = g_bnshift[j]; }

    int v0 = blockIdx.x * 64;
    for (int n = 0; n < 64; n += 2) {
        int va = v0 + n;
        int vb = va + 1;
        if (j < 64) {
            if (va < NN) {
                float x = g_RST[(size_t)va * DD + j];
                m_s[0][j] = fmaxf(fmaf(x, sc, sh), 0.f);
            }
            if (vb < NN) {
                float x = g_RST[(size_t)vb * DD + j];
                m_s[1][j] = fmaxf(fmaf(x, sc, sh), 0.f);
            }
        } else if (j < 128) {
            int jj = j - 64;
            if (va < NN) h_s[0][jj] = g_H[(size_t)va * DD + jj];
            if (vb < NN) h_s[1][jj] = g_H[(size_t)vb * DD + jj];
        }
        __syncthreads();

        unsigned long long giA = 0ull, ghA = 0ull, giB = 0ull, ghB = 0ull;
        const unsigned long long* mA = reinterpret_cast<const unsigned long long*>(m_s[0]);
        const unsigned long long* hA = reinterpret_cast<const unsigned long long*>(h_s[0]);
        const unsigned long long* mB = reinterpret_cast<const unsigned long long*>(m_s[1]);
        const unsigned long long* hB = reinterpret_cast<const unsigned long long*>(h_s[1]);
#pragma unroll
        for (int q = 0; q < 32; ++q) {
            giA = fma2(mA[q], wih[q], giA);
            ghA = fma2(hA[q], whh[q], ghA);
            giB = fma2(mB[q], wih[q], giB);
            ghB = fma2(hB[q], whh[q], ghB);
        }
        {
            float2 g1 = unpack2(giA); gi_s[0][j] = g1.x + g1.y + bi;
            float2 g2 = unpack2(ghA); gh_s[0][j] = g2.x + g2.y + bh;
            float2 g3 = unpack2(giB); gi_s[1][j] = g3.x + g3.y + bi;
            float2 g4 = unpack2(ghB); gh_s[1][j] = g4.x + g4.y + bh;
        }
        __syncthreads();

        if (j < 128) {
            int s = (j < 64) ? 0 : 1;
            int jj = j - s * 64;
            int v = v0 + n + s;
            if (v < NN) {
                float r = 1.f / (1.f + expf(-(gi_s[s][jj] + gh_s[s][jj])));
                float z = 1.f / (1.f + expf(-(gi_s[s][64 + jj] + gh_s[s][64 + jj])));
                float nn = tanhf(gi_s[s][128 + jj] + r * gh_s[s][128 + jj]);
                float hnew = (1.f - z) * nn + z * h_s[s][jj];
                g_H[(size_t)v * DD + jj] = hnew;
                if (last) out[(size_t)v * DD + jj] = hnew;
            }
        }
        __syncthreads();
    }
}

// ---------------- launch ----------------
extern "C" void kernel_launch(void* const* d_in, const int* in_sizes, int n_in,
                              void* d_out, int out_size) {
    const float *node_feats = nullptr, *edge_feats = nullptr;
    const float *W_proj = nullptr, *b_proj = nullptr;
    const float *W_e1 = nullptr, *b_e1 = nullptr, *W_e2 = nullptr, *b_e2 = nullptr;
    const float *conv_bias = nullptr, *bn_gamma = nullptr, *bn_beta = nullptr;
    const float *W_ih = nullptr, *W_hh = nullptr, *b_ih = nullptr, *b_hh = nullptr;
    const int *src = nullptr, *dst = nullptr;
    int c60000 = 0, c64 = 0, c12288 = 0, c192 = 0;

    for (int i = 0; i < n_in; ++i) {
        const void* p = d_in[i];
        switch (in_sizes[i]) {
            case 1110000: node_feats = (const float*)p; break;
            case 720000:  edge_feats = (const float*)p; break;
            case 60000:   if (c60000++ == 0) src = (const int*)p; else dst = (const int*)p; break;
            case 4736:    W_proj = (const float*)p; break;
            case 64:
                if (c64 == 0) b_proj = (const float*)p;
                else if (c64 == 1) conv_bias = (const float*)p;
                else if (c64 == 2) bn_gamma = (const float*)p;
                else bn_beta = (const float*)p;
                ++c64; break;
            case 1536:    W_e1 = (const float*)p; break;
            case 128:     b_e1 = (const float*)p; break;
            case 524288:  W_e2 = (const float*)p; break;
            case 4096:    b_e2 = (const float*)p; break;
            case 12288:   if (c12288++ == 0) W_ih = (const float*)p; else W_hh = (const float*)p; break;
            case 192:     if (c192++ == 0) b_ih = (const float*)p; else b_hh = (const float*)p; break;
            default: break;
        }
    }
    if (!node_feats || !edge_feats || !src || !dst || !W_proj || !b_proj || !W_e1 ||
        !b_e1 || !W_e2 || !b_e2 || !conv_bias || !bn_gamma || !bn_beta || !W_ih ||
        !W_hh || !b_ih || !b_hh)
        return;

    cudaFuncSetAttribute(k_edge2t, cudaFuncAttributeMaxDynamicSharedMemorySize,
                         E2_SMEM_TOTAL);

    // prep: CSR sort by dst, then fused edge1/proj/w2cvt, then EW build
    k_zero<<<(NN + 255) / 256, 256>>>();
    k_cnt<<<(NE + 255) / 256, 256>>>(dst);
    k_scan<<<1, 1024>>>();
    k_scatter<<<(NE + 255) / 256, 256>>>(src, dst);
    k_prep<<<PREP_BLOCKS, 128>>>(edge_feats, W_e1, b_e1,
                                 node_feats, W_proj, b_proj, W_e2);
    k_edge2t<<<(NE + 127) / 128, 256, E2_SMEM_TOTAL>>>(b_e2);

    // message-passing steps: fused msg+mean+bias+BN-stats, then GRU
    int mblk = (NN + 63) / 64;
    for (int s = 0; s < NSTEPS; ++s) {
        k_msgf<<<mblk, 512>>>(conv_bias, bn_gamma, bn_beta);
        k_gru<<<(NN + 63) / 64, 192>>>(W_ih, W_hh, b_ih, b_hh,
                                       (float*)d_out, s == NSTEPS - 1);
    }
}

// round 17
// speedup vs baseline: 1.2035x; 1.2035x over previous
#include <cuda_runtime.h>
#include <cuda_fp16.h>
#include <cuda_bf16.h>
#include <math.h>

// ---------------- problem constants ----------------
#define NN      15000
#define NE      60000
#define DIN     74
#define DEI     12
#define DD      64
#define EH      128
#define NSTEPS  6
#define BN_EPS  1e-5f

// ---------------- scratch (device globals; allocation-free) ----------------
__device__ float  g_H[NN * DD];
__device__ __half g_Ah[NE * EH];                 // edge hidden a (fp16)
__device__ __half g_W2h[EH * DD * DD];           // W_e2 fp16 (1 MB, L2-resident)
__device__ __half g_EWh[(size_t)NE * DD * DD];   // per-edge matrices, fp16 (492 MB)
__device__ float  g_RST[NN * DD];
__device__ float  g_deg[NN];
__device__ float  g_invdeg[NN];
__device__ float  g_colsum[DD];
__device__ float  g_colsq[DD];
__device__ float  g_bnscale[DD];
__device__ float  g_bnshift[DD];
__device__ unsigned g_bnctr;

// ---------------- f32x2 packed-FMA helpers (Blackwell FFMA2) ----------------
__device__ __forceinline__ unsigned long long fma2(unsigned long long a,
                                                   unsigned long long b,
                                                   unsigned long long c) {
    unsigned long long d;
    asm("fma.rn.f32x2 %0, %1, %2, %3;" : "=l"(d) : "l"(a), "l"(b), "l"(c));
    return d;
}
__device__ __forceinline__ float2 unpack2(unsigned long long v) {
    float2 f;
    asm("mov.b64 {%0, %1}, %2;" : "=f"(f.x), "=f"(f.y) : "l"(v));
    return f;
}

// ---------------- tensor-core helpers ----------------
__device__ __forceinline__ unsigned smem_u32(const void* p) {
    return (unsigned)__cvta_generic_to_shared(p);
}
__device__ __forceinline__ void ldmA(unsigned& a0, unsigned& a1, unsigned& a2,
                                     unsigned& a3, unsigned addr) {
    asm volatile("ldmatrix.sync.aligned.m8n8.x4.shared.b16 {%0,%1,%2,%3}, [%4];"
                 : "=r"(a0), "=r"(a1), "=r"(a2), "=r"(a3) : "r"(addr));
}
__device__ __forceinline__ void ldmBT(unsigned& b0, unsigned& b1, unsigned& b2,
                                      unsigned& b3, unsigned addr) {
    asm volatile("ldmatrix.sync.aligned.m8n8.x4.trans.shared.b16 {%0,%1,%2,%3}, [%4];"
                 : "=r"(b0), "=r"(b1), "=r"(b2), "=r"(b3) : "r"(addr));
}
__device__ __forceinline__ void mma16816(float& c0, float& c1, float& c2, float& c3,
                                         unsigned a0, unsigned a1, unsigned a2,
                                         unsigned a3, unsigned b0, unsigned b1) {
    asm volatile(
        "mma.sync.aligned.m16n8k16.row.col.f32.f16.f16.f32 "
        "{%0,%1,%2,%3}, {%4,%5,%6,%7}, {%8,%9}, {%0,%1,%2,%3};"
        : "+f"(c0), "+f"(c1), "+f"(c2), "+f"(c3)
        : "r"(a0), "r"(a1), "r"(a2), "r"(a3), "r"(b0), "r"(b1));
}

// ---------------- fused init: zero deg/RST/colsums/ctr ----------------
__global__ void k_zero() {
    int i = blockIdx.x * blockDim.x + threadIdx.x;
    if (i < NN * DD) g_RST[i] = 0.f;
    if (i < NN) g_deg[i] = 0.f;
    if (i < DD) { g_colsum[i] = 0.f; g_colsq[i] = 0.f; }
    if (i == 0) g_bnctr = 0u;
}

__global__ void k_deg(const int* __restrict__ dst) {
    int e = blockIdx.x * blockDim.x + threadIdx.x;
    if (e < NE) atomicAdd(&g_deg[dst[e]], 1.f);
}

__global__ void k_invdeg() {
    int i = blockIdx.x * blockDim.x + threadIdx.x;
    if (i < NN) {
        float d = g_deg[i];
        g_invdeg[i] = (d > 0.f) ? (1.f / d) : 0.f;
    }
}

// ---------------- fused static precompute: edge1 + proj + w2cvt -------------
#define PREP_PROJ_BLKS  ((NN + 1) / 2)
#define PREP_W2_BLKS    (EH * DD * DD / 128)
#define PREP_BLOCKS     (NE + PREP_PROJ_BLKS + PREP_W2_BLKS)

__global__ void __launch_bounds__(128) k_prep(
    const float* __restrict__ ef, const float* __restrict__ W1,
    const float* __restrict__ b1,
    const float* __restrict__ nf, const float* __restrict__ Wp,
    const float* __restrict__ bp,
    const float* __restrict__ W2) {
    int b = blockIdx.x;
    int tid = threadIdx.x;
    if (b < NE) {
        int k = tid;
        const float* row = ef + (size_t)b * DEI;
        float acc = b1[k];
#pragma unroll
        for (int i = 0; i < DEI; ++i)
            acc = fmaf(__ldg(&row[i]), __ldg(&W1[i * EH + k]), acc);
        g_Ah[(size_t)b * EH + k] = __float2half_rn(fmaxf(acc, 0.f));
    } else if (b < NE + PREP_PROJ_BLKS) {
        int r = (b - NE) * 2 + (tid >> 6);
        int o = tid & 63;
        if (r < NN) {
            const float* row = nf + (size_t)r * DIN;
            float acc = bp[o];
#pragma unroll 2
            for (int i = 0; i < DIN; ++i)
                acc = fmaf(__ldg(&row[i]), __ldg(&Wp[i * DD + o]), acc);
            g_H[(size_t)r * DD + o] = fmaxf(acc, 0.f);
        }
    } else {
        int idx = (b - NE - PREP_PROJ_BLKS) * 128 + tid;
        g_W2h[idx] = __float2half_rn(W2[idx]);
    }
}

// ---------------- edge MLP stage 2 on tensor cores --------------------------
#define E2_AS_BYTES    (128 * 136 * 2)
#define E2_B_BYTES     (128 * 72 * 2)
#define E2_BT_BYTES    (E2_B_BYTES + 256)
#define E2_STAGE_OFF   (E2_AS_BYTES + 2 * E2_BT_BYTES)
#define E2_STAGE_BYTES (128 * 72 * 2)
#define E2_SMEM_TOTAL  (E2_STAGE_OFF + E2_STAGE_BYTES)   // 90624 -> 2 blocks/SM

__device__ __forceinline__ void e2_stage(char* sm, int p, int ntile, int tid,
                                         const float* __restrict__ b2) {
    __half* B = reinterpret_cast<__half*>(sm + E2_AS_BYTES + p * E2_BT_BYTES);
    float* bias = reinterpret_cast<float*>(sm + E2_AS_BYTES + p * E2_BT_BYTES + E2_B_BYTES);
    int n0 = ntile * 64;
#pragma unroll
    for (int r = 0; r < 4; ++r) {
        int i = tid + r * 256;
        int row = i >> 3, seg = i & 7;
        const __half* src = &g_W2h[(size_t)row * 4096 + n0 + seg * 8];
        unsigned da = smem_u32(B + row * 72 + seg * 8);
        asm volatile("cp.async.cg.shared.global [%0], [%1], 16;" :: "r"(da), "l"(src));
    }
    if (tid < 16) {
        const float* src = b2 + n0 + tid * 4;
        unsigned da = smem_u32(bias + tid * 4);
        asm volatile("cp.async.cg.shared.global [%0], [%1], 16;" :: "r"(da), "l"(src));
    }
    asm volatile("cp.async.commit_group;");
}

__global__ void __launch_bounds__(256, 2) k_edge2t(const float* __restrict__ b2) {
    extern __shared__ char sm[];
    __half (*As)[136] = reinterpret_cast<__half(*)[136]>(sm);
    __half* stg = reinterpret_cast<__half*>(sm + E2_STAGE_OFF);

    int tid  = threadIdx.x;
    int warp = tid >> 5;
    int lane = tid & 31;
    int warpM = warp >> 1;
    int warpN = warp & 1;
    int e0 = blockIdx.x * 128;

#pragma unroll
    for (int r = 0; r < 8; ++r) {
        int i = tid + r * 256;
        int row = i >> 4, seg = i & 15;
        int e = e0 + row;
        uint4 v = (e < NE)
            ? *reinterpret_cast<const uint4*>(&g_Ah[(size_t)e * EH + seg * 8])
            : make_uint4(0u, 0u, 0u, 0u);
        *reinterpret_cast<uint4*>(&As[row][seg * 8]) = v;
    }

    e2_stage(sm, 0, 0, tid, b2);
    __syncthreads();

    unsigned afr[2][8][4];
#pragma unroll
    for (int mt = 0; mt < 2; ++mt) {
        unsigned aBase = smem_u32(&As[warpM * 32 + mt * 16 + (lane & 15)][(lane >> 4) * 8]);
#pragma unroll
        for (int ks = 0; ks < 8; ++ks)
            ldmA(afr[mt][ks][0], afr[mt][ks][1], afr[mt][ks][2], afr[mt][ks][3],
                 aBase + ks * 32);
    }

    unsigned bOff = (lane & 15) * 144 + (lane >> 4) * 16 + warpN * 64;
    int frl = warpM * 32 + (lane >> 2);
    int cb = (lane & 3) * 2;

    for (int ntile = 0; ntile < 64; ++ntile) {
        int buf = ntile & 1;
        asm volatile("cp.async.wait_group 0;");
        __syncthreads();

        if (ntile + 1 < 64)
            e2_stage(sm, buf ^ 1, ntile + 1, tid, b2);

        float acc[2][4][4];
#pragma unroll
        for (int mt = 0; mt < 2; ++mt)
#pragma unroll
            for (int t = 0; t < 4; ++t)
#pragma unroll
                for (int p = 0; p < 4; ++p) acc[mt][t][p] = 0.f;

        unsigned bBase = smem_u32(sm + E2_AS_BYTES + buf * E2_BT_BYTES) + bOff;
#pragma unroll
        for (int ks = 0; ks < 8; ++ks) {
#pragma unroll
            for (int nt = 0; nt < 2; ++nt) {
                unsigned b0, b1, b2v, b3;
                ldmBT(b0, b1, b2v, b3, bBase + ks * 16 * 144 + nt * 32);
#pragma unroll
                for (int mt = 0; mt < 2; ++mt) {
                    mma16816(acc[mt][nt * 2][0], acc[mt][nt * 2][1],
                             acc[mt][nt * 2][2], acc[mt][nt * 2][3],
                             afr[mt][ks][0], afr[mt][ks][1], afr[mt][ks][2],
                             afr[mt][ks][3], b0, b1);
                    mma16816(acc[mt][nt * 2 + 1][0], acc[mt][nt * 2 + 1][1],
                             acc[mt][nt * 2 + 1][2], acc[mt][nt * 2 + 1][3],
                             afr[mt][ks][0], afr[mt][ks][1], afr[mt][ks][2],
                             afr[mt][ks][3], b2v, b3);
                }
            }
        }

        const float* bias = reinterpret_cast<const float*>(
            sm + E2_AS_BYTES + buf * E2_BT_BYTES + E2_B_BYTES);
#pragma unroll
        for (int mt = 0; mt < 2; ++mt) {
            int lr = frl + mt * 16;
#pragma unroll
            for (int cg = 0; cg < 4; ++cg) {
                int lc = warpN * 32 + cg * 8 + cb;
                float2 bv = *reinterpret_cast<const float2*>(&bias[lc]);
                __half2 h0 = __floats2half2_rn(acc[mt][cg][0] + bv.x,
                                               acc[mt][cg][1] + bv.y);
                __half2 h1 = __floats2half2_rn(acc[mt][cg][2] + bv.x,
                                               acc[mt][cg][3] + bv.y);
                *reinterpret_cast<__half2*>(&stg[lr * 72 + lc]) = h0;
                *reinterpret_cast<__half2*>(&stg[(lr + 8) * 72 + lc]) = h1;
            }
        }
        __syncthreads();

        int n0 = ntile * 64;
#pragma unroll
        for (int r = 0; r < 4; ++r) {
            int c = tid + r * 256;
            int row = c >> 3, seg = c & 7;
            if (e0 + row < NE) {
                uint4 v = *reinterpret_cast<const uint4*>(&stg[row * 72 + seg * 8]);
                __stcs(reinterpret_cast<uint4*>(
                           &g_EWh[(size_t)(e0 + row) * 4096 + n0 + seg * 8]), v);
            }
        }
    }
}

// ---------------- per-step kernels ----------------
// msg[e] = h[src[e]] @ EW[e]; 512 threads = 16 edges/block; full-warp atomics.
__global__ void __launch_bounds__(512) k_msg(const int* __restrict__ src,
                                             const int* __restrict__ dst) {
    __shared__ float hbuf[16][64];
    int w = threadIdx.x >> 5;
    int lane = threadIdx.x & 31;
    int e = blockIdx.x * 16 + w;
    if (e >= NE) return;
    int s = src[e];
    int d = dst[e];
    hbuf[w][lane]      = g_H[(size_t)s * DD + lane];
    hbuf[w][lane + 32] = g_H[(size_t)s * DD + 32 + lane];
    __syncwarp();

    int r = lane >> 3;
    int c = lane & 7;
    const uint4* M = reinterpret_cast<const uint4*>(g_EWh + (size_t)e * 4096) + c;
    float acc[8];
#pragma unroll
    for (int q = 0; q < 8; ++q) acc[q] = 0.f;

#pragma unroll
    for (int t = 0; t < 16; ++t) {
        int i = t * 4 + r;
        uint4 wv = __ldcs(&M[i * 8]);
        float hv = hbuf[w][i];
        const __half2* hp = reinterpret_cast<const __half2*>(&wv);
#pragma unroll
        for (int q = 0; q < 4; ++q) {
            float2 f = __half22float2(hp[q]);
            acc[2 * q]     = fmaf(hv, f.x, acc[2 * q]);
            acc[2 * q + 1] = fmaf(hv, f.y, acc[2 * q + 1]);
        }
    }
#pragma unroll
    for (int q = 0; q < 8; ++q) {
        acc[q] += __shfl_xor_sync(0xffffffffu, acc[q], 8);
        acc[q] += __shfl_xor_sync(0xffffffffu, acc[q], 16);
    }
    {
        int q0 = r * 2;
        float* out = g_RST + (size_t)d * DD + c * 8 + q0;
        atomicAdd(out,     acc[q0]);
        atomicAdd(out + 1, acc[q0 + 1]);
    }
}

// rst = rst*invdeg + conv_bias, column sums; LAST block finalizes BN params
__global__ void k_bnred(const float* __restrict__ cbias,
                        const float* __restrict__ gamma,
                        const float* __restrict__ beta) {
    int o = threadIdx.x & 63;
    int ty = threadIdx.x >> 6;
    int v0 = blockIdx.x * 128;
    float cb = cbias[o];
    float s = 0.f, s2 = 0.f;
#pragma unroll 4
    for (int t = 0; t < 32; ++t) {
        int v = v0 + ty + t * 4;
        if (v < NN) {
            size_t idx = (size_t)v * DD + o;
            float x = fmaf(g_RST[idx], g_invdeg[v], cb);
            g_RST[idx] = x;
            s += x;
            s2 = fmaf(x, x, s2);
        }
    }
    __shared__ float ss[4][64], ss2[4][64];
    __shared__ int s_last;
    ss[ty][o] = s;
    ss2[ty][o] = s2;
    __syncthreads();
    if (ty == 0) {
        s  = ss[0][o] + ss[1][o] + ss[2][o] + ss[3][o];
        s2 = ss2[0][o] + ss2[1][o] + ss2[2][o] + ss2[3][o];
        atomicAdd(&g_colsum[o], s);
        atomicAdd(&g_colsq[o], s2);
    }
    __syncthreads();
    if (threadIdx.x == 0) {
        __threadfence();
        unsigned t = atomicAdd(&g_bnctr, 1u);
        s_last = (t == gridDim.x - 1);
    }
    __syncthreads();
    if (s_last) {
        __threadfence();
        if (threadIdx.x < 64) {
            const float invn = 1.f / (float)NN;
            float mu = g_colsum[threadIdx.x] * invn;
            float var = g_colsq[threadIdx.x] * invn - mu * mu;
            float sc = gamma[threadIdx.x] * rsqrtf(var + BN_EPS);
            g_bnscale[threadIdx.x] = sc;
            g_bnshift[threadIdx.x] = beta[threadIdx.x] - mu * sc;
            g_colsum[threadIdx.x] = 0.f;
            g_colsq[threadIdx.x] = 0.f;
        }
        if (threadIdx.x == 0) g_bnctr = 0u;
    }
}

// GRU v2: double-buffered smem (2 barriers/pair) + register prefetch of the
// next pair's RST/H loads (hidden behind the fma chain). RST zeroed at prefetch.
__global__ void __launch_bounds__(192) k_gru(const float* __restrict__ W_ih,
                                             const float* __restrict__ W_hh,
                                             const float* __restrict__ b_ih,
                                             const float* __restrict__ b_hh,
                                             float* __restrict__ out, int last) {
    __shared__ float m_s[2][2][64], h_s[2][2][64], gi_s[2][2][192], gh_s[2][2][192];
    int j = threadIdx.x;

    unsigned long long wih[32], whh[32];
    const unsigned long long* pih = reinterpret_cast<const unsigned long long*>(W_ih) + j * 32;
    const unsigned long long* phh = reinterpret_cast<const unsigned long long*>(W_hh) + j * 32;
#pragma unroll
    for (int q = 0; q < 32; ++q) { wih[q] = pih[q]; whh[q] = phh[q]; }
    float bi = b_ih[j], bh = b_hh[j];
    float sc = 0.f, sh = 0.f;
    if (j < 64) { sc = g_bnscale[j]; sh = g_bnshift[j]; }

    int v0 = blockIdx.x * 64;
    float pr0 = 0.f, pr1 = 0.f;

    // prefetch pair 0 (RST zeroed as consumed)
    {
        int va = v0, vb = v0 + 1;
        if (j < 64) {
            if (va < NN) { size_t ia = (size_t)va * DD + j; pr0 = g_RST[ia]; g_RST[ia] = 0.f; }
            if (vb < NN) { size_t ib = (size_t)vb * DD + j; pr1 = g_RST[ib]; g_RST[ib] = 0.f; }
        } else if (j < 128) {
            int jj = j - 64;
            if (va < NN) pr0 = g_H[(size_t)va * DD + jj];
            if (vb < NN) pr1 = g_H[(size_t)vb * DD + jj];
        }
    }

    for (int n = 0; n < 64; n += 2) {
        int pp = (n >> 1) & 1;
        if (j < 64) {
            m_s[pp][0][j] = fmaxf(fmaf(pr0, sc, sh), 0.f);
            m_s[pp][1][j] = fmaxf(fmaf(pr1, sc, sh), 0.f);
        } else if (j < 128) {
            int jj = j - 64;
            h_s[pp][0][jj] = pr0;
            h_s[pp][1][jj] = pr1;
        }
        __syncthreads();

        // prefetch pair n+2 (overlaps the fma chain below)
        if (n + 2 < 64) {
            int va = v0 + n + 2, vb = va + 1;
            pr0 = 0.f; pr1 = 0.f;
            if (j < 64) {
                if (va < NN) { size_t ia = (size_t)va * DD + j; pr0 = g_RST[ia]; g_RST[ia] = 0.f; }
                if (vb < NN) { size_t ib = (size_t)vb * DD + j; pr1 = g_RST[ib]; g_RST[ib] = 0.f; }
            } else if (j < 128) {
                int jj = j - 64;
                if (va < NN) pr0 = g_H[(size_t)va * DD + jj];
                if (vb < NN) pr1 = g_H[(size_t)vb * DD + jj];
            }
        }

        unsigned long long giA = 0ull, ghA = 0ull, giB = 0ull, ghB = 0ull;
        const unsigned long long* mA = reinterpret_cast<const unsigned long long*>(m_s[pp][0]);
        const unsigned long long* hA = reinterpret_cast<const unsigned long long*>(h_s[pp][0]);
        const unsigned long long* mB = reinterpret_cast<const unsigned long long*>(m_s[pp][1]);
        const unsigned long long* hB = reinterpret_cast<const unsigned long long*>(h_s[pp][1]);
#pragma unroll
        for (int q = 0; q < 32; ++q) {
            giA = fma2(mA[q], wih[q], giA);
            ghA = fma2(hA[q], whh[q], ghA);
            giB = fma2(mB[q], wih[q], giB);
            ghB = fma2(hB[q], whh[q], ghB);
        }
        {
            float2 g1 = unpack2(giA); gi_s[pp][0][j] = g1.x + g1.y + bi;
            float2 g2 = unpack2(ghA); gh_s[pp][0][j] = g2.x + g2.y + bh;
            float2 g3 = unpack2(giB); gi_s[pp][1][j] = g3.x + g3.y + bi;
            float2 g4 = unpack2(ghB); gh_s[pp][1][j] = g4.x + g4.y + bh;
        }
        __syncthreads();

        if (j < 128) {
            int s = (j < 64) ? 0 : 1;
            int jj = j - s * 64;
            int v = v0 + n + s;
            if (v < NN) {
                float r = 1.f / (1.f + expf(-(gi_s[pp][s][jj] + gh_s[pp][s][jj])));
                float z = 1.f / (1.f + expf(-(gi_s[pp][s][64 + jj] + gh_s[pp][s][64 + jj])));
                float nn = tanhf(gi_s[pp][s][128 + jj] + r * gh_s[pp][s][128 + jj]);
                float hnew = (1.f - z) * nn + z * h_s[pp][s][jj];
                g_H[(size_t)v * DD + jj] = hnew;
                if (last) out[(size_t)v * DD + jj] = hnew;
            }
        }
        // no trailing barrier: next pair writes the other parity buffer
    }
}

// ---------------- launch ----------------
extern "C" void kernel_launch(void* const* d_in, const int* in_sizes, int n_in,
                              void* d_out, int out_size) {
    const float *node_feats = nullptr, *edge_feats = nullptr;
    const float *W_proj = nullptr, *b_proj = nullptr;
    const float *W_e1 = nullptr, *b_e1 = nullptr, *W_e2 = nullptr, *b_e2 = nullptr;
    const float *conv_bias = nullptr, *bn_gamma = nullptr, *bn_beta = nullptr;
    const float *W_ih = nullptr, *W_hh = nullptr, *b_ih = nullptr, *b_hh = nullptr;
    const int *src = nullptr, *dst = nullptr;
    int c60000 = 0, c64 = 0, c12288 = 0, c192 = 0;

    for (int i = 0; i < n_in; ++i) {
        const void* p = d_in[i];
        switch (in_sizes[i]) {
            case 1110000: node_feats = (const float*)p; break;
            case 720000:  edge_feats = (const float*)p; break;
            case 60000:   if (c60000++ == 0) src = (const int*)p; else dst = (const int*)p; break;
            case 4736:    W_proj = (const float*)p; break;
            case 64:
                if (c64 == 0) b_proj = (const float*)p;
                else if (c64 == 1) conv_bias = (const float*)p;
                else if (c64 == 2) bn_gamma = (const float*)p;
                else bn_beta = (const float*)p;
                ++c64; break;
            case 1536:    W_e1 = (const float*)p; break;
            case 128:     b_e1 = (const float*)p; break;
            case 524288:  W_e2 = (const float*)p; break;
            case 4096:    b_e2 = (const float*)p; break;
            case 12288:   if (c12288++ == 0) W_ih = (const float*)p; else W_hh = (const float*)p; break;
            case 192:     if (c192++ == 0) b_ih = (const float*)p; else b_hh = (const float*)p; break;
            default: break;
        }
    }
    if (!node_feats || !edge_feats || !src || !dst || !W_proj || !b_proj || !W_e1 ||
        !b_e1 || !W_e2 || !b_e2 || !conv_bias || !bn_gamma || !bn_beta || !W_ih ||
        !W_hh || !b_ih || !b_hh)
        return;

    cudaFuncSetAttribute(k_edge2t, cudaFuncAttributeMaxDynamicSharedMemorySize,
                         E2_SMEM_TOTAL);

    // fused prep; k_edge2t stays 4th so the profiler samples it
    k_zero<<<(NN * DD + 255) / 256, 256>>>();                       // 1
    k_prep<<<PREP_BLOCKS, 128>>>(edge_feats, W_e1, b_e1,
                                 node_feats, W_proj, b_proj, W_e2); // 2
    k_deg<<<(NE + 255) / 256, 256>>>(dst);                          // 3
    k_edge2t<<<(NE + 127) / 128, 256, E2_SMEM_TOTAL>>>(b_e2);       // 4 <- profiled
    k_invdeg<<<(NN + 255) / 256, 256>>>();                          // 5

    // message-passing steps
    for (int s = 0; s < NSTEPS; ++s) {
        k_msg<<<(NE + 15) / 16, 512>>>(src, dst);
        k_bnred<<<(NN + 127) / 128, 256>>>(conv_bias, bn_gamma, bn_beta);
        k_gru<<<(NN + 63) / 64, 192>>>(W_ih, W_hh, b_ih, b_hh,
                                       (float*)d_out, s == NSTEPS - 1);
    }
}